// round 16
// baseline (speedup 1.0000x reference)
#include <cuda_runtime.h>
#include <cstdint>

// Problem constants
#define BATCH   8192
#define MSIZE   128
#define NBLK    32
#define BN      (BATCH * MSIZE)    // 1048576 elems per c-slab

// Scratch: Y[c][b][n] (tf32), Z[b][c][m]
__device__ float g_Y[(size_t)NBLK * BN];
__device__ float g_Z[(size_t)NBLK * BN];

// ---------------- helpers ----------------
__device__ __forceinline__ float tf32r(float v) {
    unsigned u;
    asm("cvt.rna.tf32.f32 %0, %1;" : "=r"(u) : "f"(v));
    return __uint_as_float(u);
}
__device__ __forceinline__ void mma_tf32(float& d0, float& d1, float& d2, float& d3,
                                         unsigned a0, unsigned a1, unsigned a2, unsigned a3,
                                         unsigned b0, unsigned b1) {
    asm volatile(
        "mma.sync.aligned.m16n8k8.row.col.f32.tf32.tf32.f32 "
        "{%0,%1,%2,%3}, {%4,%5,%6,%7}, {%8,%9}, {%0,%1,%2,%3};"
        : "+f"(d0), "+f"(d1), "+f"(d2), "+f"(d3)
        : "r"(a0), "r"(a1), "r"(a2), "r"(a3), "r"(b0), "r"(b1));
}
__device__ __forceinline__ uint32_t smem_u32(const void* p) {
    uint32_t a;
    asm("{ .reg .u64 t; cvta.to.shared.u64 t, %1; cvt.u32.u64 %0, t; }" : "=r"(a) : "l"(p));
    return a;
}
__device__ __forceinline__ void cp16(uint32_t dst, const void* src) {
    asm volatile("cp.async.cg.shared.global [%0], [%1], 16;" :: "r"(dst), "l"(src));
}

// ---------------- Stage 1 (tf32 MMA, unchanged from R14) ----------------
#define A1_LD 260
#define B1_LD 36
__global__ void __launch_bounds__(256) k1_mma(const float* __restrict__ x,
                                              const float* __restrict__ Win,
                                              const float* __restrict__ bin) {
    __shared__ float As[32 * A1_LD];
    __shared__ float Bs[32 * B1_LD];
    __shared__ float bb[32];
    const int tid = threadIdx.x;
    const size_t b0 = (size_t)blockIdx.x * 2;

    const float4* x4 = (const float4*)(x + b0 * 4096);
#pragma unroll
    for (int j = 0; j < 8; j++) {
        const int idx = tid + j * 256;
        const int bl = idx >> 10, q = idx & 1023;
        const int i = q >> 5, n4 = (q & 31) << 2;
        float4 v = x4[idx];
        v.x = tf32r(v.x); v.y = tf32r(v.y); v.z = tf32r(v.z); v.w = tf32r(v.w);
        *(float4*)&As[i * A1_LD + bl * 128 + n4] = v;
    }
    {
        const int c = tid >> 3, i4 = (tid & 7) << 2;
        float4 w = *(const float4*)&Win[c * 32 + i4];
        w.x = tf32r(w.x); w.y = tf32r(w.y); w.z = tf32r(w.z); w.w = tf32r(w.w);
        *(float4*)&Bs[c * B1_LD + i4] = w;
    }
    if (tid < 32) bb[tid] = bin[tid];
    __syncthreads();

    const int lane = tid & 31, warp = tid >> 5;
    const int g = lane >> 2, tg = lane & 3;
    const int wr = warp * 32;

    float acc[2][4][4];
#pragma unroll
    for (int rt = 0; rt < 2; rt++)
#pragma unroll
        for (int ct = 0; ct < 4; ct++)
#pragma unroll
            for (int j = 0; j < 4; j++) acc[rt][ct][j] = 0.0f;

#pragma unroll
    for (int ks = 0; ks < 4; ks++) {
        const int kk = ks * 8 + tg;
        unsigned a0[2], a1[2], a2[2], a3[2], bf0[4], bf1[4];
#pragma unroll
        for (int rt = 0; rt < 2; rt++) {
            const int r0 = wr + rt * 16 + g;
            a0[rt] = __float_as_uint(As[kk * A1_LD + r0]);
            a1[rt] = __float_as_uint(As[kk * A1_LD + r0 + 8]);
            a2[rt] = __float_as_uint(As[(kk + 4) * A1_LD + r0]);
            a3[rt] = __float_as_uint(As[(kk + 4) * A1_LD + r0 + 8]);
        }
#pragma unroll
        for (int ct = 0; ct < 4; ct++) {
            const int col = ct * 8 + g;
            bf0[ct] = __float_as_uint(Bs[col * B1_LD + ks * 8 + tg]);
            bf1[ct] = __float_as_uint(Bs[col * B1_LD + ks * 8 + tg + 4]);
        }
#pragma unroll
        for (int rt = 0; rt < 2; rt++)
#pragma unroll
            for (int ct = 0; ct < 4; ct++)
                mma_tf32(acc[rt][ct][0], acc[rt][ct][1], acc[rt][ct][2], acc[rt][ct][3],
                         a0[rt], a1[rt], a2[rt], a3[rt], bf0[ct], bf1[ct]);
    }

#pragma unroll
    for (int rt = 0; rt < 2; rt++) {
        const int rA = wr + rt * 16 + g;
        const int bl = rA >> 7, nA = rA & 127, nB = (rA + 8) & 127;
        const size_t bo = (b0 + bl) * 128;
#pragma unroll
        for (int ct = 0; ct < 4; ct++) {
            const int c0 = ct * 8 + tg * 2;
            g_Y[(size_t)c0 * BN + bo + nA]       = tf32r(acc[rt][ct][0] + bb[c0]);
            g_Y[(size_t)(c0 + 1) * BN + bo + nA] = tf32r(acc[rt][ct][1] + bb[c0 + 1]);
            g_Y[(size_t)c0 * BN + bo + nB]       = tf32r(acc[rt][ct][2] + bb[c0]);
            g_Y[(size_t)(c0 + 1) * BN + bo + nB] = tf32r(acc[rt][ct][3] + bb[c0 + 1]);
        }
    }
}

// ---------------- Stage 2 (persistent 512-thr HMMA, W resident, A double-buffered) ----
// Z[b][c][m] = sum_k Y[c][b][k] * W_mods[c][m][k] + b_mods[c][m]
// grid (16 btg x 32 c), 512 threads (16 warps, warp = 32x32 subtile), 1 CTA/SM,
// 4 b-tiles per CTA. W (all 4 k-chunks) stays in smem; A tiles stream via cp.async.
#define W_LD   36
#define A2_LD  132
#define A2_SZ  (128 * A2_LD)           // floats per A buffer
#define K2_W_OFF 0                     // 4 * 128 * W_LD = 18432 floats
#define K2_A_OFF 18432
#define K2_BB_OFF (18432 + 2 * A2_SZ)  // 18432 + 33792 = 52224
#define K2_FLOATS (K2_BB_OFF + 128)    // 52352 floats = 209408 bytes
#define BT_PER_CTA 4

__global__ void __launch_bounds__(512, 1) k2_hmma(const float* __restrict__ Wm,
                                                  const float* __restrict__ bmods) {
    extern __shared__ float sm[];
    float* Ws  = sm + K2_W_OFF;        // [kc][128 m][W_LD]
    float* As  = sm + K2_A_OFF;        // 2 x [128 r][A2_LD]
    float* bmS = sm + K2_BB_OFF;
    const uint32_t sb = smem_u32(sm);

    const int tid = threadIdx.x;
    const int c   = blockIdx.y;
    const int btg = blockIdx.x;
    const float* Ysl = g_Y + (size_t)c * BN;

    // issue cp.async for A tile 0 into buffer 0
    {
        const float4* src = (const float4*)(Ysl + (size_t)(btg * BT_PER_CTA) * 16384);
#pragma unroll
        for (int j = 0; j < 8; j++) {
            const int idx = tid + j * 512;
            const int r = idx >> 5, c4 = (idx & 31) << 2;
            cp16(sb + (uint32_t)(K2_A_OFF + r * A2_LD + c4) * 4, src + idx);
        }
        asm volatile("cp.async.commit_group;" ::: "memory");
    }
    // load W tile (tf32-rounded) into chunked-resident layout
    {
        const float4* Wsrc = (const float4*)(Wm + (size_t)c * 16384);
#pragma unroll
        for (int j = 0; j < 8; j++) {
            const int idx = tid + j * 512;          // 0..4095 float4
            const int mm = idx >> 5, f = idx & 31;  // 32 float4 per m-row
            const int kc = f >> 3, kl = (f & 7) << 2;
            float4 v = Wsrc[idx];
            v.x = tf32r(v.x); v.y = tf32r(v.y); v.z = tf32r(v.z); v.w = tf32r(v.w);
            *(float4*)&Ws[(kc * 128 + mm) * W_LD + kl] = v;
        }
    }
    if (tid < 128) bmS[tid] = bmods[c * 128 + tid];

    asm volatile("cp.async.wait_group 0;" ::: "memory");
    __syncthreads();

    const int lane = tid & 31, warp = tid >> 5;
    const int g = lane >> 2, tg = lane & 3;
    const int wr = (warp & 3) * 32;     // 4 warps over 128 rows
    const int wc = (warp >> 2) * 32;    // 4 warps over 128 cols (m)

    // bias values this thread needs (constant across tiles)
    float bv0[4], bv1[4];
#pragma unroll
    for (int ct = 0; ct < 4; ct++) {
        const int m0 = wc + ct * 8 + tg * 2;
        bv0[ct] = bmS[m0];
        bv1[ct] = bmS[m0 + 1];
    }

#pragma unroll 1
    for (int t = 0; t < BT_PER_CTA; t++) {
        const int bt = btg * BT_PER_CTA + t;
        const float* Acur = As + (t & 1) * A2_SZ;

        // issue next A tile into the other buffer (flows under the MMAs)
        if (t < BT_PER_CTA - 1) {
            const float4* src = (const float4*)(Ysl + (size_t)(bt + 1) * 16384);
            const uint32_t dstb = sb + (uint32_t)(K2_A_OFF + ((t + 1) & 1) * A2_SZ) * 4;
#pragma unroll
            for (int j = 0; j < 8; j++) {
                const int idx = tid + j * 512;
                const int r = idx >> 5, c4 = (idx & 31) << 2;
                cp16(dstb + (uint32_t)(r * A2_LD + c4) * 4, src + idx);
            }
            asm volatile("cp.async.commit_group;" ::: "memory");
        }

        float acc[2][4][4];
#pragma unroll
        for (int rt = 0; rt < 2; rt++)
#pragma unroll
            for (int ct = 0; ct < 4; ct++)
#pragma unroll
                for (int j = 0; j < 4; j++) acc[rt][ct][j] = 0.0f;

#pragma unroll 1
        for (int kc = 0; kc < 4; kc++) {
            const float* Bk = Ws + kc * 128 * W_LD;
#pragma unroll
            for (int ks = 0; ks < 4; ks++) {
                const int kA = kc * 32 + ks * 8;
                const int kB = ks * 8;
                unsigned a0[2], a1[2], a2[2], a3[2], b0[4], b1[4];
#pragma unroll
                for (int rt = 0; rt < 2; rt++) {
                    const int r0 = wr + rt * 16 + g;
                    a0[rt] = __float_as_uint(Acur[r0 * A2_LD + kA + tg]);
                    a1[rt] = __float_as_uint(Acur[(r0 + 8) * A2_LD + kA + tg]);
                    a2[rt] = __float_as_uint(Acur[r0 * A2_LD + kA + tg + 4]);
                    a3[rt] = __float_as_uint(Acur[(r0 + 8) * A2_LD + kA + tg + 4]);
                }
#pragma unroll
                for (int ct = 0; ct < 4; ct++) {
                    const int mcol = wc + ct * 8 + g;
                    b0[ct] = __float_as_uint(Bk[mcol * W_LD + kB + tg]);
                    b1[ct] = __float_as_uint(Bk[mcol * W_LD + kB + tg + 4]);
                }
#pragma unroll
                for (int rt = 0; rt < 2; rt++)
#pragma unroll
                    for (int ct = 0; ct < 4; ct++)
                        mma_tf32(acc[rt][ct][0], acc[rt][ct][1], acc[rt][ct][2], acc[rt][ct][3],
                                 a0[rt], a1[rt], a2[rt], a3[rt], b0[ct], b1[ct]);
            }
        }

        // epilogue: add bias, write Z[b][c][m]
#pragma unroll
        for (int rt = 0; rt < 2; rt++) {
            const int r0 = wr + rt * 16 + g;
            const size_t base = ((size_t)bt * 128 + r0) * 4096 + (size_t)c * 128;
#pragma unroll
            for (int ct = 0; ct < 4; ct++) {
                const int m0 = wc + ct * 8 + tg * 2;
                *(float2*)&g_Z[base + m0] =
                    make_float2(acc[rt][ct][0] + bv0[ct], acc[rt][ct][1] + bv1[ct]);
                *(float2*)&g_Z[base + 8 * 4096 + m0] =
                    make_float2(acc[rt][ct][2] + bv0[ct], acc[rt][ct][3] + bv1[ct]);
            }
        }

        if (t < BT_PER_CTA - 1) {
            asm volatile("cp.async.wait_group 0;" ::: "memory");
            __syncthreads();
        }
    }
}

// ---------------- Stage 3 (tf32 MMA, unchanged from R14) ----------------
#define A3_LD 260
#define B3_LD 36
__global__ void __launch_bounds__(256) k3_mma(const float* __restrict__ Wout,
                                              const float* __restrict__ bout,
                                              float* __restrict__ out) {
    __shared__ float As[32 * A3_LD];
    __shared__ float Bs[32 * B3_LD];
    __shared__ float bb[32];
    const int tid = threadIdx.x;
    const size_t b0 = (size_t)blockIdx.x * 2;

    const float4* z4 = (const float4*)(g_Z + b0 * 4096);
#pragma unroll
    for (int j = 0; j < 8; j++) {
        const int idx = tid + j * 256;
        const int bl = idx >> 10, q = idx & 1023;
        const int c = q >> 5, m4 = (q & 31) << 2;
        float4 v = z4[idx];
        v.x = tf32r(v.x); v.y = tf32r(v.y); v.z = tf32r(v.z); v.w = tf32r(v.w);
        *(float4*)&As[c * A3_LD + bl * 128 + m4] = v;
    }
    {
        const int o = tid >> 3, c4 = (tid & 7) << 2;
        float4 w = *(const float4*)&Wout[o * 32 + c4];
        w.x = tf32r(w.x); w.y = tf32r(w.y); w.z = tf32r(w.z); w.w = tf32r(w.w);
        *(float4*)&Bs[o * B3_LD + c4] = w;
    }
    if (tid < 32) bb[tid] = bout[tid];
    __syncthreads();

    const int lane = tid & 31, warp = tid >> 5;
    const int g = lane >> 2, tg = lane & 3;
    const int wr = warp * 32;

    float acc[2][4][4];
#pragma unroll
    for (int rt = 0; rt < 2; rt++)
#pragma unroll
        for (int ct = 0; ct < 4; ct++)
#pragma unroll
            for (int j = 0; j < 4; j++) acc[rt][ct][j] = 0.0f;

#pragma unroll
    for (int ks = 0; ks < 4; ks++) {
        const int kk = ks * 8 + tg;
        unsigned a0[2], a1[2], a2[2], a3[2], bf0[4], bf1[4];
#pragma unroll
        for (int rt = 0; rt < 2; rt++) {
            const int r0 = wr + rt * 16 + g;
            a0[rt] = __float_as_uint(As[kk * A3_LD + r0]);
            a1[rt] = __float_as_uint(As[kk * A3_LD + r0 + 8]);
            a2[rt] = __float_as_uint(As[(kk + 4) * A3_LD + r0]);
            a3[rt] = __float_as_uint(As[(kk + 4) * A3_LD + r0 + 8]);
        }
#pragma unroll
        for (int ct = 0; ct < 4; ct++) {
            const int col = ct * 8 + g;
            bf0[ct] = __float_as_uint(Bs[col * B3_LD + ks * 8 + tg]);
            bf1[ct] = __float_as_uint(Bs[col * B3_LD + ks * 8 + tg + 4]);
        }
#pragma unroll
        for (int rt = 0; rt < 2; rt++)
#pragma unroll
            for (int ct = 0; ct < 4; ct++)
                mma_tf32(acc[rt][ct][0], acc[rt][ct][1], acc[rt][ct][2], acc[rt][ct][3],
                         a0[rt], a1[rt], a2[rt], a3[rt], bf0[ct], bf1[ct]);
    }

#pragma unroll
    for (int rt = 0; rt < 2; rt++) {
        const int rA = wr + rt * 16 + g;
        const int bl = rA >> 7, mA = rA & 127, mB = (rA + 8) & 127;
        float* orow = out + (b0 + bl) * 4096;
#pragma unroll
        for (int ct = 0; ct < 4; ct++) {
            const int o0 = ct * 8 + tg * 2;
            const float bu0 = bb[o0], bu1 = bb[o0 + 1];
            *(float2*)&orow[mA * 32 + o0] = make_float2(acc[rt][ct][0] + bu0, acc[rt][ct][1] + bu1);
            *(float2*)&orow[mB * 32 + o0] = make_float2(acc[rt][ct][2] + bu0, acc[rt][ct][3] + bu1);
        }
    }
}

// ---------------- launch ----------------
extern "C" void kernel_launch(void* const* d_in, const int* in_sizes, int n_in,
                              void* d_out, int out_size) {
    (void)in_sizes; (void)n_in; (void)out_size;
    const float* x      = (const float*)d_in[0];
    const float* W_in   = (const float*)d_in[1];
    const float* b_in   = (const float*)d_in[2];
    const float* W_mods = (const float*)d_in[3];
    const float* b_mods = (const float*)d_in[4];
    const float* W_out  = (const float*)d_in[5];
    const float* b_out  = (const float*)d_in[6];
    float* out = (float*)d_out;

    const int smem2 = K2_FLOATS * (int)sizeof(float);  // 209408 bytes
    cudaFuncSetAttribute(k2_hmma, cudaFuncAttributeMaxDynamicSharedMemorySize, smem2);

    k1_mma <<<BATCH / 2, 256>>>(x, W_in, b_in);
    k2_hmma<<<dim3(64 / BT_PER_CTA, NBLK), 512, smem2>>>(W_mods, b_mods);
    k3_mma <<<BATCH / 2, 256>>>(W_out, b_out, out);
}